// round 2
// baseline (speedup 1.0000x reference)
#include <cuda_runtime.h>
#include <math.h>

// Problem constants
constexpr int T_STEPS = 28;
constexpr int B_TOT   = 16384;
constexpr int X_DIM   = 28;
constexpr int H_DIM   = 100;
constexpr int Z_DIM   = 16;
constexpr int TB      = 32;              // batch rows per block
constexpr int NBLK    = B_TOT / TB;      // 512 blocks
constexpr int NTHR    = 256;             // 8 warps

// Per-block partial sums (kl, nll) — deterministic 2-pass reduction, no atomics.
__device__ float g_part[NBLK * 2];

// ---------------------------------------------------------------------------
// Activation codes
enum { ACT_LIN = 0, ACT_RELU = 1, ACT_SIG = 2, ACT_SP = 3 };

__device__ __forceinline__ float act_apply(float v, int ACT) {
    if (ACT == ACT_RELU) return fmaxf(v, 0.f);
    if (ACT == ACT_SIG)  return 1.f / (1.f + expf(-v));
    if (ACT == ACT_SP)   return fmaxf(v, 0.f) + log1pf(expf(-fabsf(v)));
    return v;
}

// ---------------------------------------------------------------------------
// GEMM: out[o][row] = act( sum_k W[o][k]*in[k][row] + b[o] )
// Activations are feat-major in smem: act[k*32 + lane], lane = batch row.
// Each participating warp computes 8 outputs at a time (register tile).
// Weights: broadcast LDG.128 (all lanes same address), L2-resident.
// KA4/KB4 = K/4 for the two concatenated input segments (B may be absent).
template <int KA4, int KB4, int ACT>
__device__ __forceinline__ void gemm8(
    const float* __restrict__ W, const float* __restrict__ bias,
    const float* __restrict__ actA, const float* __restrict__ actB,
    float* __restrict__ out, int Nout, int wsel, int nw, int lane)
{
    constexpr int K = 4 * (KA4 + KB4);
    for (int o0 = wsel * 8; o0 < Nout; o0 += nw * 8) {
        float acc[8];
        const float* wr[8];
#pragma unroll
        for (int i = 0; i < 8; i++) {
            int o = o0 + i; if (o > Nout - 1) o = Nout - 1;  // clamp (safe reads)
            wr[i] = W + (size_t)o * K;
            acc[i] = 0.f;
        }
#pragma unroll 4
        for (int k4 = 0; k4 < KA4; k4++) {
            const int kk = 4 * k4;
            float a0 = actA[(kk + 0) * TB + lane];
            float a1 = actA[(kk + 1) * TB + lane];
            float a2 = actA[(kk + 2) * TB + lane];
            float a3 = actA[(kk + 3) * TB + lane];
#pragma unroll
            for (int i = 0; i < 8; i++) {
                float4 w = *reinterpret_cast<const float4*>(wr[i] + kk);
                acc[i] = fmaf(w.x, a0, acc[i]);
                acc[i] = fmaf(w.y, a1, acc[i]);
                acc[i] = fmaf(w.z, a2, acc[i]);
                acc[i] = fmaf(w.w, a3, acc[i]);
            }
        }
        if (KB4 > 0) {
#pragma unroll 4
            for (int k4 = 0; k4 < KB4; k4++) {
                const int kk = 4 * k4;
                float a0 = actB[(kk + 0) * TB + lane];
                float a1 = actB[(kk + 1) * TB + lane];
                float a2 = actB[(kk + 2) * TB + lane];
                float a3 = actB[(kk + 3) * TB + lane];
#pragma unroll
                for (int i = 0; i < 8; i++) {
                    float4 w = *reinterpret_cast<const float4*>(wr[i] + 4 * KA4 + kk);
                    acc[i] = fmaf(w.x, a0, acc[i]);
                    acc[i] = fmaf(w.y, a1, acc[i]);
                    acc[i] = fmaf(w.z, a2, acc[i]);
                    acc[i] = fmaf(w.w, a3, acc[i]);
                }
            }
        }
#pragma unroll
        for (int i = 0; i < 8; i++) {
            int o = o0 + i;
            if (o < Nout) {
                float v = acc[i] + bias[o];
                out[o * TB + lane] = act_apply(v, ACT);
            }
        }
    }
}

// 4-output accumulate-only dot over a feat-major smem operand.
// W row stride ldw, starting row row0, starting column col0 (multiple of 4).
template <int K4>
__device__ __forceinline__ void dot4_acc(
    float acc[4], const float* __restrict__ W, int ldw, int row0, int col0,
    const float* __restrict__ act, int lane)
{
    const float* wr[4];
#pragma unroll
    for (int i = 0; i < 4; i++) wr[i] = W + (size_t)(row0 + i) * ldw + col0;
#pragma unroll 5
    for (int k4 = 0; k4 < K4; k4++) {
        const int kk = 4 * k4;
        float a0 = act[(kk + 0) * TB + lane];
        float a1 = act[(kk + 1) * TB + lane];
        float a2 = act[(kk + 2) * TB + lane];
        float a3 = act[(kk + 3) * TB + lane];
#pragma unroll
        for (int i = 0; i < 4; i++) {
            float4 w = *reinterpret_cast<const float4*>(wr[i] + kk);
            acc[i] = fmaf(w.x, a0, acc[i]);
            acc[i] = fmaf(w.y, a1, acc[i]);
            acc[i] = fmaf(w.z, a2, acc[i]);
            acc[i] = fmaf(w.w, a3, acc[i]);
        }
    }
}

// GRUCell(input=[pz, px], h) -> hn. Nout = 100, warp handles 4 j's per group.
__device__ __forceinline__ void gru_step(
    const float* __restrict__ Wih, const float* __restrict__ Whh,
    const float* __restrict__ bih, const float* __restrict__ bhh,
    const float* __restrict__ pz, const float* __restrict__ px,
    const float* __restrict__ h, float* __restrict__ hn, int warp, int lane)
{
    for (int j0 = warp * 4; j0 < H_DIM; j0 += 32) {
        float r[4], u[4], ni[4], nh[4];
#pragma unroll
        for (int i = 0; i < 4; i++) {
            int j = j0 + i;
            r[i]  = bih[j]         + bhh[j];
            u[i]  = bih[H_DIM + j] + bhh[H_DIM + j];
            ni[i] = bih[2 * H_DIM + j];
            nh[i] = bhh[2 * H_DIM + j];
        }
        // gi = Wih @ [pz, px],  gh = Whh @ h
        dot4_acc<25>(r,  Wih, 200, j0,             0,     pz, lane);
        dot4_acc<25>(r,  Wih, 200, j0,             H_DIM, px, lane);
        dot4_acc<25>(r,  Whh, 100, j0,             0,     h,  lane);
        dot4_acc<25>(u,  Wih, 200, H_DIM + j0,     0,     pz, lane);
        dot4_acc<25>(u,  Wih, 200, H_DIM + j0,     H_DIM, px, lane);
        dot4_acc<25>(u,  Whh, 100, H_DIM + j0,     0,     h,  lane);
        dot4_acc<25>(ni, Wih, 200, 2 * H_DIM + j0, 0,     pz, lane);
        dot4_acc<25>(ni, Wih, 200, 2 * H_DIM + j0, H_DIM, px, lane);
        dot4_acc<25>(nh, Whh, 100, 2 * H_DIM + j0, 0,     h,  lane);
#pragma unroll
        for (int i = 0; i < 4; i++) {
            int j = j0 + i;
            float rr = 1.f / (1.f + expf(-r[i]));
            float uu = 1.f / (1.f + expf(-u[i]));
            float nn = tanhf(ni[i] + rr * nh[i]);
            hn[j * TB + lane] = (1.f - uu) * nn + uu * h[j * TB + lane];
        }
    }
}

// ---------------------------------------------------------------------------
// Main persistent kernel: block owns 32 batch rows for all 28 timesteps.
__global__ void __launch_bounds__(NTHR, 2) vrnn_main(
    const float* __restrict__ x,      const float* __restrict__ eps,
    const float* __restrict__ Wpx,    const float* __restrict__ bpx,
    const float* __restrict__ Wpz,    const float* __restrict__ bpz,
    const float* __restrict__ Wp1,    const float* __restrict__ bp1,
    const float* __restrict__ Wp_mu,  const float* __restrict__ bp_mu,
    const float* __restrict__ Wp_sig, const float* __restrict__ bp_sig,
    const float* __restrict__ We1,    const float* __restrict__ be1,
    const float* __restrict__ We_mu,  const float* __restrict__ be_mu,
    const float* __restrict__ We_sig, const float* __restrict__ be_sig,
    const float* __restrict__ Wd1,    const float* __restrict__ bd1,
    const float* __restrict__ Wd2,    const float* __restrict__ bd2,
    const float* __restrict__ Wd3,    const float* __restrict__ bd3,
    const float* __restrict__ Wih,    const float* __restrict__ Whh,
    const float* __restrict__ bih,    const float* __restrict__ bhh)
{
    extern __shared__ float s[];
    // feat-major [feat][TB] buffers
    float* xs   = s;                    // 28*32
    float* es   = xs   + X_DIM * TB;    // 16*32
    float* h0   = es   + Z_DIM * TB;    // 100*32
    float* h1   = h0   + H_DIM * TB;    // 100*32
    float* px   = h1   + H_DIM * TB;    // 100*32
    float* pz   = px   + H_DIM * TB;    // 100*32
    float* bufA = pz   + H_DIM * TB;    // he / hd1
    float* bufB = bufA + H_DIM * TB;    // hp / hd2
    float* emu  = bufB + H_DIM * TB;    // 16*32
    float* esg  = emu  + Z_DIM * TB;
    float* pmu  = esg  + Z_DIM * TB;
    float* psg  = pmu  + Z_DIM * TB;
    float* zb   = psg  + Z_DIM * TB;
    float* prb  = zb   + Z_DIM * TB;    // 28*32 probs

    const int tid  = threadIdx.x;
    const int lane = tid & 31;
    const int warp = tid >> 5;
    const int b0   = blockIdx.x * TB;

    // h0 = 0
    for (int i = tid; i < H_DIM * TB; i += NTHR) h0[i] = 0.f;

    float kl_acc = 0.f, nll_acc = 0.f;   // meaningful in warp 0 (lane == row)
    float* hc = h0;
    float* hn = h1;

    for (int t = 0; t < T_STEPS; t++) {
        // Stage inputs (fully coalesced gmem reads)
        const float* xg = x   + ((size_t)t * B_TOT + b0) * X_DIM;
        const float* eg = eps + ((size_t)t * B_TOT + b0) * Z_DIM;
        for (int i = tid; i < X_DIM * TB; i += NTHR) {
            int r = i / X_DIM, k = i % X_DIM;
            xs[k * TB + r] = xg[i];
        }
        for (int i = tid; i < Z_DIM * TB; i += NTHR) {
            int r = i / Z_DIM, k = i % Z_DIM;
            es[k * TB + r] = eg[i];
        }
        __syncthreads();

        // 1. px = relu(Wpx x + b)                         [100, K=28]
        gemm8<7, 0, ACT_RELU>(Wpx, bpx, xs, nullptr, px, H_DIM, warp, 8, lane);
        __syncthreads();

        // 2. he = relu(We1 [px;h] + b)  -> bufA           [100, K=200]
        gemm8<25, 25, ACT_RELU>(We1, be1, px, hc, bufA, H_DIM, warp, 8, lane);
        // 3. hp = relu(Wp1 h + b)       -> bufB           [100, K=100]
        gemm8<25, 0, ACT_RELU>(Wp1, bp1, hc, nullptr, bufB, H_DIM, warp, 8, lane);
        __syncthreads();

        // 4. fused small heads: enc_mu/enc_sig from he, pr_mu/pr_sig from hp
        if (warp < 2)
            gemm8<25, 0, ACT_LIN>(We_mu, be_mu, bufA, nullptr, emu, Z_DIM, warp, 2, lane);
        else if (warp < 4)
            gemm8<25, 0, ACT_SP >(We_sig, be_sig, bufA, nullptr, esg, Z_DIM, warp - 2, 2, lane);
        else if (warp < 6)
            gemm8<25, 0, ACT_LIN>(Wp_mu, bp_mu, bufB, nullptr, pmu, Z_DIM, warp - 4, 2, lane);
        else
            gemm8<25, 0, ACT_SP >(Wp_sig, bp_sig, bufB, nullptr, psg, Z_DIM, warp - 6, 2, lane);
        __syncthreads();

        // 5. z = enc_mu + sqrt(enc_sig)*eps
        for (int i = tid; i < Z_DIM * TB; i += NTHR)
            zb[i] = emu[i] + sqrtf(esg[i]) * es[i];
        __syncthreads();

        // 6. pz = relu(Wpz z + b)                         [100, K=16]
        gemm8<4, 0, ACT_RELU>(Wpz, bpz, zb, nullptr, pz, H_DIM, warp, 8, lane);
        __syncthreads();

        // 7. hd1 = relu(Wd1 [pz;h] + b) -> bufA           [100, K=200]
        gemm8<25, 25, ACT_RELU>(Wd1, bd1, pz, hc, bufA, H_DIM, warp, 8, lane);
        __syncthreads();

        // 8. hd2 = relu(Wd2 hd1 + b)    -> bufB           [100, K=100]
        gemm8<25, 0, ACT_RELU>(Wd2, bd2, bufA, nullptr, bufB, H_DIM, warp, 8, lane);
        __syncthreads();

        // 9. probs = sigmoid(Wd3 hd2 + b)                 [28, K=100]
        gemm8<25, 0, ACT_SIG>(Wd3, bd3, bufB, nullptr, prb, X_DIM, warp, 8, lane);
        // 10. GRU -> hn (independent of stage 9 buffers)
        gru_step(Wih, Whh, bih, bhh, pz, px, hc, hn, warp, lane);
        __syncthreads();

        // 11. KL + NLL per row (warp 0, lane == row)
        if (warp == 0) {
            float klr = 0.f;
#pragma unroll
            for (int zk = 0; zk < Z_DIM; zk++) {
                float esv = esg[zk * TB + lane];
                float emv = emu[zk * TB + lane];
                float pmv = pmu[zk * TB + lane];
                float psv = psg[zk * TB + lane] + 1e-10f;
                float d = emv - pmv;
                klr += 0.5f * (2.f * logf(psv) - 2.f * logf(esv)
                               + (esv * esv + d * d) / (psv * psv) - 1.f);
            }
            kl_acc += klr;
            float nr = 0.f;
#pragma unroll
            for (int xk = 0; xk < X_DIM; xk++) {
                float p  = prb[xk * TB + lane];
                float xv = xs[xk * TB + lane];
                nr -= xv * logf(p + 1e-10f) + (1.f - xv) * logf(1.f - p + 1e-10f);
            }
            nll_acc += nr;
        }

        // swap h buffers; barrier also protects xs/emu/... reuse next step
        float* tmp = hc; hc = hn; hn = tmp;
        __syncthreads();
    }

    // block partial: reduce 32 rows (warp 0) and store
    if (warp == 0) {
#pragma unroll
        for (int off = 16; off > 0; off >>= 1) {
            kl_acc  += __shfl_down_sync(0xffffffffu, kl_acc,  off);
            nll_acc += __shfl_down_sync(0xffffffffu, nll_acc, off);
        }
        if (lane == 0) {
            g_part[blockIdx.x * 2 + 0] = kl_acc;
            g_part[blockIdx.x * 2 + 1] = nll_acc;
        }
    }
}

// Deterministic final reduction: one block, fixed tree order.
__global__ void vrnn_reduce(float* __restrict__ out)
{
    __shared__ float sk[NTHR], sn[NTHR];
    int tid = threadIdx.x;
    float k = 0.f, n = 0.f;
    for (int i = tid; i < NBLK; i += NTHR) {
        k += g_part[2 * i + 0];
        n += g_part[2 * i + 1];
    }
    sk[tid] = k; sn[tid] = n;
    __syncthreads();
    for (int s = NTHR / 2; s > 0; s >>= 1) {
        if (tid < s) { sk[tid] += sk[tid + s]; sn[tid] += sn[tid + s]; }
        __syncthreads();
    }
    if (tid == 0) {
        const float invB = 1.f / (float)B_TOT;
        out[0] = sk[0] * invB;   // sum over t of kl.sum(1).mean()
        out[1] = sn[0] * invB;   // sum over t of nll.sum(1).mean()
    }
}

// ---------------------------------------------------------------------------
extern "C" void kernel_launch(void* const* d_in, const int* in_sizes, int n_in,
                              void* d_out, int out_size)
{
    (void)in_sizes; (void)n_in; (void)out_size;
    const float* x      = (const float*)d_in[0];
    const float* eps    = (const float*)d_in[1];
    const float* Wpx    = (const float*)d_in[2];
    const float* bpx    = (const float*)d_in[3];
    const float* Wpz    = (const float*)d_in[4];
    const float* bpz    = (const float*)d_in[5];
    const float* Wp1    = (const float*)d_in[6];
    const float* bp1    = (const float*)d_in[7];
    const float* Wp_mu  = (const float*)d_in[8];
    const float* bp_mu  = (const float*)d_in[9];
    const float* Wp_sig = (const float*)d_in[10];
    const float* bp_sig = (const float*)d_in[11];
    const float* We1    = (const float*)d_in[12];
    const float* be1    = (const float*)d_in[13];
    const float* We_mu  = (const float*)d_in[14];
    const float* be_mu  = (const float*)d_in[15];
    const float* We_sig = (const float*)d_in[16];
    const float* be_sig = (const float*)d_in[17];
    const float* Wd1    = (const float*)d_in[18];
    const float* bd1    = (const float*)d_in[19];
    const float* Wd2    = (const float*)d_in[20];
    const float* bd2    = (const float*)d_in[21];
    const float* Wd3    = (const float*)d_in[22];
    const float* bd3    = (const float*)d_in[23];
    const float* Wih    = (const float*)d_in[24];
    const float* Whh    = (const float*)d_in[25];
    const float* bih    = (const float*)d_in[26];
    const float* bhh    = (const float*)d_in[27];
    float* out = (float*)d_out;

    const int smem_bytes =
        (X_DIM * TB + Z_DIM * TB + 6 * H_DIM * TB + 5 * Z_DIM * TB + X_DIM * TB)
        * (int)sizeof(float);   // = 96,256 bytes

    cudaFuncSetAttribute(vrnn_main,
                         cudaFuncAttributeMaxDynamicSharedMemorySize, smem_bytes);

    vrnn_main<<<NBLK, NTHR, smem_bytes>>>(
        x, eps, Wpx, bpx, Wpz, bpz, Wp1, bp1, Wp_mu, bp_mu, Wp_sig, bp_sig,
        We1, be1, We_mu, be_mu, We_sig, be_sig, Wd1, bd1, Wd2, bd2, Wd3, bd3,
        Wih, Whh, bih, bhh);

    vrnn_reduce<<<1, NTHR>>>(out);
}

// round 3
// speedup vs baseline: 1.7588x; 1.7588x over previous
#include <cuda_runtime.h>
#include <math.h>

using ull = unsigned long long;

// Problem constants
constexpr int T_STEPS = 28;
constexpr int B_TOT   = 16384;
constexpr int X_DIM   = 28;
constexpr int H_DIM   = 100;
constexpr int Z_DIM   = 16;
constexpr int TB      = 64;              // batch rows per block (2 per lane)
constexpr int NBLK    = B_TOT / TB;      // 256 blocks
constexpr int NTHR    = 256;             // 8 warps

__device__ float        g_part[NBLK * 2];
__device__ unsigned int g_done;

enum { ACT_LIN = 0, ACT_RELU = 1, ACT_SIG = 2, ACT_SP = 3 };

__device__ __forceinline__ float act_apply(float v, int ACT) {
    if (ACT == ACT_RELU) return fmaxf(v, 0.f);
    if (ACT == ACT_SIG)  return 1.f / (1.f + expf(-v));
    if (ACT == ACT_SP)   return fmaxf(v, 0.f) + log1pf(expf(-fabsf(v)));
    return v;
}

// ---- packed f32x2 helpers (Blackwell FFMA2 path) --------------------------
__device__ __forceinline__ ull b2(float v) {
    ull r; asm("mov.b64 %0,{%1,%1};" : "=l"(r) : "f"(v)); return r;
}
__device__ __forceinline__ ull fma2(ull a, ull b, ull c) {
    ull d; asm("fma.rn.f32x2 %0,%1,%2,%3;" : "=l"(d) : "l"(a), "l"(b), "l"(c));
    return d;
}
__device__ __forceinline__ float2 unpk(ull v) {
    float2 f; asm("mov.b64 {%0,%1},%2;" : "=f"(f.x), "=f"(f.y) : "l"(v)); return f;
}
__device__ __forceinline__ ull pk(float x, float y) {
    ull r; asm("mov.b64 %0,{%1,%2};" : "=l"(r) : "f"(x), "f"(y)); return r;
}

// ---------------------------------------------------------------------------
// GEMM chunk: NO outputs per warp, activations feat-major packed float2:
// act_u64[k*32 + lane] = rows (lane, lane+32) of feature k.
// out[o][rows] = act( sum_k W[o][k]*in[k][rows] + b[o] )
template <int NO>
__device__ __forceinline__ void gemm_chunk(
    const float* __restrict__ W, int K, const float* __restrict__ bias,
    const float* __restrict__ actA, int K4A,
    const float* __restrict__ actB, int K4B,
    float* __restrict__ out, int o0, int act, int lane)
{
    ull acc[NO];
    const float* wr[NO];
#pragma unroll
    for (int i = 0; i < NO; i++) { wr[i] = W + (size_t)(o0 + i) * K; acc[i] = 0ull; }

    const ull* aA = reinterpret_cast<const ull*>(actA);
#pragma unroll 4
    for (int k4 = 0; k4 < K4A; k4++) {
        const int kk = 4 * k4;
        ull a0 = aA[(kk + 0) * 32 + lane];
        ull a1 = aA[(kk + 1) * 32 + lane];
        ull a2 = aA[(kk + 2) * 32 + lane];
        ull a3 = aA[(kk + 3) * 32 + lane];
#pragma unroll
        for (int i = 0; i < NO; i++) {
            float4 w = *reinterpret_cast<const float4*>(wr[i] + kk);
            acc[i] = fma2(b2(w.x), a0, acc[i]);
            acc[i] = fma2(b2(w.y), a1, acc[i]);
            acc[i] = fma2(b2(w.z), a2, acc[i]);
            acc[i] = fma2(b2(w.w), a3, acc[i]);
        }
    }
    if (actB) {
        const ull* aB = reinterpret_cast<const ull*>(actB);
        const int kw0 = 4 * K4A;
#pragma unroll 4
        for (int k4 = 0; k4 < K4B; k4++) {
            const int kk = 4 * k4;
            ull a0 = aB[(kk + 0) * 32 + lane];
            ull a1 = aB[(kk + 1) * 32 + lane];
            ull a2 = aB[(kk + 2) * 32 + lane];
            ull a3 = aB[(kk + 3) * 32 + lane];
#pragma unroll
            for (int i = 0; i < NO; i++) {
                float4 w = *reinterpret_cast<const float4*>(wr[i] + kw0 + kk);
                acc[i] = fma2(b2(w.x), a0, acc[i]);
                acc[i] = fma2(b2(w.y), a1, acc[i]);
                acc[i] = fma2(b2(w.z), a2, acc[i]);
                acc[i] = fma2(b2(w.w), a3, acc[i]);
            }
        }
    }
    ull* o64 = reinterpret_cast<ull*>(out);
#pragma unroll
    for (int i = 0; i < NO; i++) {
        float bv = bias[o0 + i];
        float2 v = unpk(acc[i]);
        float vx = act_apply(v.x + bv, act);
        float vy = act_apply(v.y + bv, act);
        o64[(o0 + i) * 32 + lane] = pk(vx, vy);
    }
}

// Nout = 100 partition: warps 0-3 -> 12 outputs (8+4), warps 4-7 -> 13 (8+5).
__device__ __forceinline__ void gemm100(
    const float* __restrict__ W, int K, const float* __restrict__ bias,
    const float* __restrict__ aA, int K4A, const float* __restrict__ aB, int K4B,
    float* __restrict__ out, int act, int warp, int lane)
{
    if (warp < 4) {
        int o0 = warp * 12;
        gemm_chunk<8>(W, K, bias, aA, K4A, aB, K4B, out, o0,     act, lane);
        gemm_chunk<4>(W, K, bias, aA, K4A, aB, K4B, out, o0 + 8, act, lane);
    } else {
        int o0 = 48 + (warp - 4) * 13;
        gemm_chunk<8>(W, K, bias, aA, K4A, aB, K4B, out, o0,     act, lane);
        gemm_chunk<5>(W, K, bias, aA, K4A, aB, K4B, out, o0 + 8, act, lane);
    }
}

// GRU segment: accumulate 3 gate-pairs (rows j0,j0+1 at gate offsets 0/100/200)
// over a K4*4-wide slice of activations starting at weight column col0.
__device__ __forceinline__ void gru_seg(
    ull& A0, ull& A1, ull& B0, ull& B1, ull& C0, ull& C1,
    const float* __restrict__ W, int ldw, int j0, int col0,
    const float* __restrict__ act, int K4, int lane)
{
    const float* p0 = W + (size_t)(j0)       * ldw + col0;
    const float* p1 = p0 + ldw;
    const float* p2 = W + (size_t)(100 + j0) * ldw + col0;
    const float* p3 = p2 + ldw;
    const float* p4 = W + (size_t)(200 + j0) * ldw + col0;
    const float* p5 = p4 + ldw;
    const ull* A = reinterpret_cast<const ull*>(act);
#pragma unroll 5
    for (int k4 = 0; k4 < K4; k4++) {
        const int kk = 4 * k4;
        ull a0 = A[(kk + 0) * 32 + lane];
        ull a1 = A[(kk + 1) * 32 + lane];
        ull a2 = A[(kk + 2) * 32 + lane];
        ull a3 = A[(kk + 3) * 32 + lane];
        float4 w;
        w = *reinterpret_cast<const float4*>(p0 + kk);
        A0 = fma2(b2(w.x), a0, A0); A0 = fma2(b2(w.y), a1, A0);
        A0 = fma2(b2(w.z), a2, A0); A0 = fma2(b2(w.w), a3, A0);
        w = *reinterpret_cast<const float4*>(p1 + kk);
        A1 = fma2(b2(w.x), a0, A1); A1 = fma2(b2(w.y), a1, A1);
        A1 = fma2(b2(w.z), a2, A1); A1 = fma2(b2(w.w), a3, A1);
        w = *reinterpret_cast<const float4*>(p2 + kk);
        B0 = fma2(b2(w.x), a0, B0); B0 = fma2(b2(w.y), a1, B0);
        B0 = fma2(b2(w.z), a2, B0); B0 = fma2(b2(w.w), a3, B0);
        w = *reinterpret_cast<const float4*>(p3 + kk);
        B1 = fma2(b2(w.x), a0, B1); B1 = fma2(b2(w.y), a1, B1);
        B1 = fma2(b2(w.z), a2, B1); B1 = fma2(b2(w.w), a3, B1);
        w = *reinterpret_cast<const float4*>(p4 + kk);
        C0 = fma2(b2(w.x), a0, C0); C0 = fma2(b2(w.y), a1, C0);
        C0 = fma2(b2(w.z), a2, C0); C0 = fma2(b2(w.w), a3, C0);
        w = *reinterpret_cast<const float4*>(p5 + kk);
        C1 = fma2(b2(w.x), a0, C1); C1 = fma2(b2(w.y), a1, C1);
        C1 = fma2(b2(w.z), a2, C1); C1 = fma2(b2(w.w), a3, C1);
    }
}

__device__ __forceinline__ float sigf(float v) { return 1.f / (1.f + expf(-v)); }

// ---------------------------------------------------------------------------
__global__ void __launch_bounds__(NTHR, 1) vrnn_main(
    const float* __restrict__ x,      const float* __restrict__ eps,
    const float* __restrict__ Wpx,    const float* __restrict__ bpx,
    const float* __restrict__ Wpz,    const float* __restrict__ bpz,
    const float* __restrict__ Wp1,    const float* __restrict__ bp1,
    const float* __restrict__ Wp_mu,  const float* __restrict__ bp_mu,
    const float* __restrict__ Wp_sig, const float* __restrict__ bp_sig,
    const float* __restrict__ We1,    const float* __restrict__ be1,
    const float* __restrict__ We_mu,  const float* __restrict__ be_mu,
    const float* __restrict__ We_sig, const float* __restrict__ be_sig,
    const float* __restrict__ Wd1,    const float* __restrict__ bd1,
    const float* __restrict__ Wd2,    const float* __restrict__ bd2,
    const float* __restrict__ Wd3,    const float* __restrict__ bd3,
    const float* __restrict__ Wih,    const float* __restrict__ Whh,
    const float* __restrict__ bih,    const float* __restrict__ bhh,
    float* __restrict__ out)
{
    extern __shared__ float s[];
    // all feat-major packed: f2buf[(k*32+lane)*2 + half], half = row>=32
    float* xs   = s;                     // 28*64
    float* es   = xs   + X_DIM * TB;     // 16*64
    float* h0   = es   + Z_DIM * TB;     // 100*64
    float* h1   = h0   + H_DIM * TB;
    float* px   = h1   + H_DIM * TB;
    float* pz   = px   + H_DIM * TB;
    float* bufA = pz   + H_DIM * TB;
    float* bufB = bufA + H_DIM * TB;
    float* emu  = bufB + H_DIM * TB;     // 16*64
    float* esg  = emu  + Z_DIM * TB;
    float* pmu  = esg  + Z_DIM * TB;
    float* psg  = pmu  + Z_DIM * TB;
    float* zb   = psg  + Z_DIM * TB;
    float* prb  = zb   + Z_DIM * TB;     // 28*64

    __shared__ int s_last;

    const int tid  = threadIdx.x;
    const int lane = tid & 31;
    const int warp = tid >> 5;
    const int b0   = blockIdx.x * TB;

    for (int i = tid; i < H_DIM * TB; i += NTHR) h0[i] = 0.f;

    float kl_acc = 0.f, nll_acc = 0.f;
    float* hc = h0;
    float* hn = h1;

    for (int t = 0; t < T_STEPS; t++) {
        // ---- stage inputs into packed feat-major layout
        const float* xg = x   + ((size_t)t * B_TOT + b0) * X_DIM;
        const float* eg = eps + ((size_t)t * B_TOT + b0) * Z_DIM;
        for (int i = tid; i < X_DIM * TB; i += NTHR) {
            int r = i / X_DIM, k = i % X_DIM;
            xs[(k * 32 + (r & 31)) * 2 + (r >> 5)] = xg[i];
        }
        for (int i = tid; i < Z_DIM * TB; i += NTHR) {
            int r = i / Z_DIM, k = i % Z_DIM;
            es[(k * 32 + (r & 31)) * 2 + (r >> 5)] = eg[i];
        }
        __syncthreads();

        // 1. px = relu(Wpx x + b)                  [100, K=28]
        gemm100(Wpx, 28, bpx, xs, 7, nullptr, 0, px, ACT_RELU, warp, lane);
        __syncthreads();

        // 2. he = relu(We1 [px;h]) -> bufA         [100, K=200]
        gemm100(We1, 200, be1, px, 25, hc, 25, bufA, ACT_RELU, warp, lane);
        // 3. hp = relu(Wp1 h) -> bufB              [100, K=100]
        gemm100(Wp1, 100, bp1, hc, 25, nullptr, 0, bufB, ACT_RELU, warp, lane);
        __syncthreads();

        // 4. heads: enc_mu/enc_sig(he), pr_mu/pr_sig(hp); 2 warps each, 8 outs
        {
            int m = warp >> 1, o0 = (warp & 1) * 8;
            if (m == 0)
                gemm_chunk<8>(We_mu, 100, be_mu, bufA, 25, nullptr, 0, emu, o0, ACT_LIN, lane);
            else if (m == 1)
                gemm_chunk<8>(We_sig, 100, be_sig, bufA, 25, nullptr, 0, esg, o0, ACT_SP, lane);
            else if (m == 2)
                gemm_chunk<8>(Wp_mu, 100, bp_mu, bufB, 25, nullptr, 0, pmu, o0, ACT_LIN, lane);
            else
                gemm_chunk<8>(Wp_sig, 100, bp_sig, bufB, 25, nullptr, 0, psg, o0, ACT_SP, lane);
        }
        __syncthreads();

        // 5. z = enc_mu + sqrt(enc_sig)*eps  (layout-agnostic elementwise)
        for (int i = tid; i < Z_DIM * TB; i += NTHR)
            zb[i] = emu[i] + sqrtf(esg[i]) * es[i];
        __syncthreads();

        // 6. pz = relu(Wpz z + b)                  [100, K=16]
        gemm100(Wpz, 16, bpz, zb, 4, nullptr, 0, pz, ACT_RELU, warp, lane);
        __syncthreads();

        // 7. hd1 = relu(Wd1 [pz;h]) -> bufA        [100, K=200]
        gemm100(Wd1, 200, bd1, pz, 25, hc, 25, bufA, ACT_RELU, warp, lane);
        __syncthreads();

        // 8. hd2 = relu(Wd2 hd1) -> bufB           [100, K=100]
        gemm100(Wd2, 100, bd2, bufA, 25, nullptr, 0, bufB, ACT_RELU, warp, lane);
        __syncthreads();

        // 9. probs = sigmoid(Wd3 hd2 + b)          [28, K=100]; warps 0-6
        if (warp < 7)
            gemm_chunk<4>(Wd3, 100, bd3, bufB, 25, nullptr, 0, prb, warp * 4, ACT_SIG, lane);

        // 10. GRU: 2 outputs per group, 50 groups over 8 warps
        for (int g = warp; g < 50; g += 8) {
            const int j0 = 2 * g;
            ull r0 = b2(bih[j0]             + bhh[j0]);
            ull r1 = b2(bih[j0 + 1]         + bhh[j0 + 1]);
            ull u0 = b2(bih[100 + j0]       + bhh[100 + j0]);
            ull u1 = b2(bih[100 + j0 + 1]   + bhh[100 + j0 + 1]);
            ull n0 = b2(bih[200 + j0]);
            ull n1 = b2(bih[200 + j0 + 1]);
            ull m0 = b2(bhh[200 + j0]);
            ull m1 = b2(bhh[200 + j0 + 1]);
            gru_seg(r0, r1, u0, u1, n0, n1, Wih, 200, j0, 0,   pz, 25, lane);
            gru_seg(r0, r1, u0, u1, n0, n1, Wih, 200, j0, 100, px, 25, lane);
            gru_seg(r0, r1, u0, u1, m0, m1, Whh, 100, j0, 0,   hc, 25, lane);
            const ull* h64 = reinterpret_cast<const ull*>(hc);
            ull* hn64 = reinterpret_cast<ull*>(hn);
#pragma unroll
            for (int d = 0; d < 2; d++) {
                float2 R = unpk(d ? r1 : r0);
                float2 U = unpk(d ? u1 : u0);
                float2 N = unpk(d ? n1 : n0);
                float2 M = unpk(d ? m1 : m0);
                float2 H = unpk(h64[(j0 + d) * 32 + lane]);
                float rr0 = sigf(R.x), rr1 = sigf(R.y);
                float uu0 = sigf(U.x), uu1 = sigf(U.y);
                float nn0 = tanhf(N.x + rr0 * M.x);
                float nn1 = tanhf(N.y + rr1 * M.y);
                float o0v = (1.f - uu0) * nn0 + uu0 * H.x;
                float o1v = (1.f - uu1) * nn1 + uu1 * H.y;
                hn64[(j0 + d) * 32 + lane] = pk(o0v, o1v);
            }
        }
        __syncthreads();

        // 11. KL (z-features split over warps) + NLL (x-features split)
        {
            const ull* Emu = (const ull*)emu; const ull* Esg = (const ull*)esg;
            const ull* Pmu = (const ull*)pmu; const ull* Psg = (const ull*)psg;
            for (int zk = warp; zk < Z_DIM; zk += 8) {
                float2 esv = unpk(Esg[zk * 32 + lane]);
                float2 emv = unpk(Emu[zk * 32 + lane]);
                float2 pmv = unpk(Pmu[zk * 32 + lane]);
                float2 psv = unpk(Psg[zk * 32 + lane]);
                {
                    float ps = psv.x + 1e-10f, d = emv.x - pmv.x;
                    kl_acc += 0.5f * (2.f * logf(ps) - 2.f * logf(esv.x)
                                      + (esv.x * esv.x + d * d) / (ps * ps) - 1.f);
                }
                {
                    float ps = psv.y + 1e-10f, d = emv.y - pmv.y;
                    kl_acc += 0.5f * (2.f * logf(ps) - 2.f * logf(esv.y)
                                      + (esv.y * esv.y + d * d) / (ps * ps) - 1.f);
                }
            }
            const ull* Pr = (const ull*)prb; const ull* Xs = (const ull*)xs;
            for (int xk = warp; xk < X_DIM; xk += 8) {
                float2 p = unpk(Pr[xk * 32 + lane]);
                float2 xv = unpk(Xs[xk * 32 + lane]);
                nll_acc -= xv.x * logf(p.x + 1e-10f) + (1.f - xv.x) * logf(1.f - p.x + 1e-10f);
                nll_acc -= xv.y * logf(p.y + 1e-10f) + (1.f - xv.y) * logf(1.f - p.y + 1e-10f);
            }
        }

        { float* tmp = hc; hc = hn; hn = tmp; }
        __syncthreads();   // protects xs/prb/head-bufs before next staging
    }

    // ---- block partial: warp shuffle + cross-warp sum
#pragma unroll
    for (int off = 16; off > 0; off >>= 1) {
        kl_acc  += __shfl_down_sync(0xffffffffu, kl_acc,  off);
        nll_acc += __shfl_down_sync(0xffffffffu, nll_acc, off);
    }
    if (lane == 0) { s[warp] = kl_acc; s[8 + warp] = nll_acc; }
    __syncthreads();
    if (tid == 0) {
        float k = 0.f, n = 0.f;
        for (int w = 0; w < 8; w++) { k += s[w]; n += s[8 + w]; }
        g_part[2 * blockIdx.x + 0] = k;
        g_part[2 * blockIdx.x + 1] = n;
        __threadfence();
        unsigned v = atomicAdd(&g_done, 1u);
        s_last = (v == (unsigned)(gridDim.x - 1)) ? 1 : 0;
    }
    __syncthreads();

    // ---- last block performs deterministic fixed-order final reduction
    if (s_last) {
        float k = g_part[2 * tid + 0];   // NBLK == NTHR == 256
        float n = g_part[2 * tid + 1];
        s[tid] = k; s[256 + tid] = n;
        __syncthreads();
        for (int st = 128; st > 0; st >>= 1) {
            if (tid < st) { s[tid] += s[tid + st]; s[256 + tid] += s[256 + tid + st]; }
            __syncthreads();
        }
        if (tid == 0) {
            const float invB = 1.f / (float)B_TOT;
            out[0] = s[0] * invB;
            out[1] = s[256] * invB;
            g_done = 0;                  // reset for next graph replay
        }
    }
}

// ---------------------------------------------------------------------------
extern "C" void kernel_launch(void* const* d_in, const int* in_sizes, int n_in,
                              void* d_out, int out_size)
{
    (void)in_sizes; (void)n_in; (void)out_size;
    const float* x      = (const float*)d_in[0];
    const float* eps    = (const float*)d_in[1];
    const float* Wpx    = (const float*)d_in[2];
    const float* bpx    = (const float*)d_in[3];
    const float* Wpz    = (const float*)d_in[4];
    const float* bpz    = (const float*)d_in[5];
    const float* Wp1    = (const float*)d_in[6];
    const float* bp1    = (const float*)d_in[7];
    const float* Wp_mu  = (const float*)d_in[8];
    const float* bp_mu  = (const float*)d_in[9];
    const float* Wp_sig = (const float*)d_in[10];
    const float* bp_sig = (const float*)d_in[11];
    const float* We1    = (const float*)d_in[12];
    const float* be1    = (const float*)d_in[13];
    const float* We_mu  = (const float*)d_in[14];
    const float* be_mu  = (const float*)d_in[15];
    const float* We_sig = (const float*)d_in[16];
    const float* be_sig = (const float*)d_in[17];
    const float* Wd1    = (const float*)d_in[18];
    const float* bd1    = (const float*)d_in[19];
    const float* Wd2    = (const float*)d_in[20];
    const float* bd2    = (const float*)d_in[21];
    const float* Wd3    = (const float*)d_in[22];
    const float* bd3    = (const float*)d_in[23];
    const float* Wih    = (const float*)d_in[24];
    const float* Whh    = (const float*)d_in[25];
    const float* bih    = (const float*)d_in[26];
    const float* bhh    = (const float*)d_in[27];
    float* out = (float*)d_out;

    const int smem_floats =
        2 * X_DIM * TB + Z_DIM * TB + 6 * H_DIM * TB + 5 * Z_DIM * TB;
    const int smem_bytes = smem_floats * (int)sizeof(float);   // 192,512 B

    cudaFuncSetAttribute(vrnn_main,
                         cudaFuncAttributeMaxDynamicSharedMemorySize, smem_bytes);

    vrnn_main<<<NBLK, NTHR, smem_bytes>>>(
        x, eps, Wpx, bpx, Wpz, bpz, Wp1, bp1, Wp_mu, bp_mu, Wp_sig, bp_sig,
        We1, be1, We_mu, be_mu, We_sig, be_sig, Wd1, bd1, Wd2, bd2, Wd3, bd3,
        Wih, Whh, bih, bhh, out);
}